// round 5
// baseline (speedup 1.0000x reference)
#include <cuda_runtime.h>
#include <cuda_fp16.h>
#include <stdint.h>
#include <string.h>

// ---------------- problem constants ----------------
#define B_   2
#define N_   512
#define D_   64
#define H_   128
#define OUT_ 64
#define CPG  18                  // i-stride: CTAs per (b, j-block) group
#define GRID_MAIN (B_ * 4 * CPG) // 144 CTAs, ~1 per SM

// ---------------- device scratch (no allocs allowed) ----------------
__device__ __align__(16) __half g_xa [B_ * N_ * H_];   // x @ W1[:D]       (fp16)
__device__ __align__(16) __half g_xbp[B_ * N_ * H_];   // x @ W1[D:] + b1  (fp16)
__device__ float g_part[GRID_MAIN * H_];               // per-CTA pooled partials

__device__ __forceinline__ __half2 as_h2(uint32_t u) { __half2 h; memcpy(&h, &u, 4); return h; }
__device__ __forceinline__ uint32_t as_u32(__half2 h) { uint32_t u; memcpy(&u, &h, 4); return u; }

// relu(a + b) on packed half2
__device__ __forceinline__ uint32_t relu_add2(uint32_t a, uint32_t b) {
    __half2 z = __float2half2_rn(0.f);
    return as_u32(__hmax2(__hadd2(as_h2(a), as_h2(b)), z));
}

// m16n8k16 row.col fp16 -> fp32 HMMA (baseline PTX, works on sm_103)
__device__ __forceinline__ void mma16816(float* c, const uint32_t* a, uint32_t b0, uint32_t b1) {
    asm volatile(
        "mma.sync.aligned.m16n8k16.row.col.f32.f16.f16.f32 "
        "{%0,%1,%2,%3}, {%4,%5,%6,%7}, {%8,%9}, {%0,%1,%2,%3};"
        : "+f"(c[0]), "+f"(c[1]), "+f"(c[2]), "+f"(c[3])
        : "r"(a[0]), "r"(a[1]), "r"(a[2]), "r"(a[3]), "r"(b0), "r"(b1));
}

// ---------------- SMEM layout (dynamic) ----------------
// W2F : 0      32768  (W2 fragments, [k8][nt16][lane32] x 8B)
// XA  : 32768  34816  (128 rows x 272B padded fp16)
// RED : 67584  2048   (8 warps x 64 cols fp32)
#define SOFF_W2F 0
#define SOFF_XA  32768
#define SOFF_RED 67584
#define XA_STRIDE 272
#define SMEM_BYTES (67584 + 2048)

// =====================================================================
// Kernel 1: prep — xa = x @ W1[:64] (fp16), xbp = x @ W1[64:] + b1 (fp16)
// =====================================================================
__global__ void __launch_bounds__(128) prep_kernel(const float* __restrict__ x,
                                                   const float* __restrict__ W1,
                                                   const float* __restrict__ b1) {
    __shared__ float xs[8][64];
    int h = threadIdx.x;
    int row0 = blockIdx.x * 8;

    for (int q = h; q < 8 * 64; q += 128)
        xs[q >> 6][q & 63] = x[row0 * 64 + q];

    float wa[64], wb[64];
    #pragma unroll
    for (int d = 0; d < 64; d++) {
        wa[d] = W1[d * H_ + h];
        wb[d] = W1[(d + 64) * H_ + h];
    }
    float bb = b1[h];
    __syncthreads();

    #pragma unroll 1
    for (int rr = 0; rr < 8; rr++) {
        float sa = 0.f, sb = 0.f;
        #pragma unroll
        for (int d = 0; d < 64; d++) {
            sa += xs[rr][d] * wa[d];
            sb += xs[rr][d] * wb[d];
        }
        int row = row0 + rr;
        g_xa [row * H_ + h] = __float2half(sa);
        g_xbp[row * H_ + h] = __float2half(sb + bb);
    }
}

// =====================================================================
// Kernel 2: main — per (b, jb, cig) CTA, loop i-tiles (i = cig + t*CPG):
//   A-fragments a = relu(xa[j] + xb[i]) built in registers (fragment layout)
//   acc = a @ W2 via mma.sync (fp32 register accumulators)
//   pooled += relu(acc + b2), per-CTA partial written to g_part (deterministic)
// =====================================================================
__global__ void __launch_bounds__(256, 1) main_kernel(const float* __restrict__ W2,
                                                      const float* __restrict__ b2) {
    extern __shared__ char smem[];

    int tid  = threadIdx.x;
    int wid  = tid >> 5;
    int lane = tid & 31;
    int tig  = lane & 3;      // threadID in group (n-parity pair / k-pair selector)
    int g    = lane >> 2;     // groupID (row / col within 8)
    int wn   = wid >> 2;      // warp col half: 0 -> cols 0..63, 1 -> 64..127
    int wm   = wid & 3;       // warp row quarter: rows wm*32 .. wm*32+31

    int grp = blockIdx.x / CPG;   // 0..7 : (b, jb)
    int cig = blockIdx.x % CPG;
    int b   = grp >> 2;
    int jb  = grp & 3;
    int ntiles = (N_ - cig + CPG - 1) / CPG;   // 28 or 29

    // --- pack W2 into fragment-ordered smem: entry (k, nt, lane) -> 8 bytes ---
    // b-frag reg0 = (W2[k16+tig*2][col], W2[k16+tig*2+1][col]); reg1 = rows +8. col = nt*8+g.
    for (int idx = tid; idx < 8 * 16 * 32; idx += 256) {
        int li = idx & 31, nt = (idx >> 5) & 15, k = idx >> 9;
        int ltig = li & 3, lg = li >> 2;
        int col = nt * 8 + lg;
        int r0 = k * 16 + ltig * 2;
        uint32_t v0 = as_u32(__floats2half2_rn(W2[r0 * H_ + col],       W2[(r0 + 1) * H_ + col]));
        uint32_t v1 = as_u32(__floats2half2_rn(W2[(r0 + 8) * H_ + col], W2[(r0 + 9) * H_ + col]));
        *(uint2*)(smem + SOFF_W2F + idx * 8) = make_uint2(v0, v1);
    }

    // --- xa tile for (b, jb): 128 rows x 128 fp16, padded to 272B stride ---
    {
        const float4* xag = (const float4*)(g_xa + (size_t)(b * N_ + jb * 128) * H_);
        for (int q = tid; q < 128 * 16; q += 256) {
            int r = q >> 4, f = q & 15;
            *(float4*)(smem + SOFF_XA + r * XA_STRIDE + f * 16) = xag[q];
        }
    }

    // --- per-thread b2 fragment biases ---
    float b2c[8][2];
    #pragma unroll
    for (int n = 0; n < 8; n++) {
        int col = wn * 64 + n * 8 + tig * 2;
        b2c[n][0] = b2[col];
        b2c[n][1] = b2[col + 1];
    }

    __syncthreads();

    // --- xa LDS base addresses for the 4 fragment rows this thread reads ---
    // rows: wm*32 + mt*16 + g (+8); cols: k*16 + tig*2 (+8)  [half2 loads]
    const char* xa_base = smem + SOFF_XA + (wm * 32 + g) * XA_STRIDE + tig * 4;
    const char* xa_r[4] = {
        xa_base,                     // mt0, row g
        xa_base + 8 * XA_STRIDE,     // mt0, row g+8
        xa_base + 16 * XA_STRIDE,    // mt1, row g
        xa_base + 24 * XA_STRIDE     // mt1, row g+8
    };
    const char* w2f_base = smem + SOFF_W2F + (size_t)(wn * 8) * 32 * 8 + lane * 8;

    const uint32_t* xbp_rows = (const uint32_t*)(g_xbp + (size_t)(b * N_) * H_);

    float pooled[8][2];
    #pragma unroll
    for (int n = 0; n < 8; n++) { pooled[n][0] = 0.f; pooled[n][1] = 0.f; }

    // xb loader: 16 half2 regs for one i-row (words k*8+tig and k*8+tig+4)
    auto load_xb = [&](uint32_t* xb, int i) {
        const uint32_t* row = xbp_rows + (size_t)i * (H_ / 2);
        #pragma unroll
        for (int k = 0; k < 8; k++) {
            xb[k * 2]     = __ldg(row + k * 8 + tig);
            xb[k * 2 + 1] = __ldg(row + k * 8 + tig + 4);
        }
    };

    auto compute_tile = [&](const uint32_t* xb) {
        float acc[2][8][4];
        #pragma unroll
        for (int mt = 0; mt < 2; mt++)
            #pragma unroll
            for (int n = 0; n < 8; n++)
                #pragma unroll
                for (int c = 0; c < 4; c++) acc[mt][n][c] = 0.f;

        #pragma unroll
        for (int k = 0; k < 8; k++) {
            uint32_t a[2][4];
            uint32_t xb0 = xb[k * 2], xb1 = xb[k * 2 + 1];
            #pragma unroll
            for (int mt = 0; mt < 2; mt++) {
                const char* p0 = xa_r[mt * 2]     + k * 32;
                const char* p1 = xa_r[mt * 2 + 1] + k * 32;
                uint32_t x0 = *(const uint32_t*)(p0);       // row g,   cols 2t
                uint32_t x1 = *(const uint32_t*)(p1);       // row g+8, cols 2t
                uint32_t x2 = *(const uint32_t*)(p0 + 16);  // row g,   cols 2t+8
                uint32_t x3 = *(const uint32_t*)(p1 + 16);  // row g+8, cols 2t+8
                a[mt][0] = relu_add2(x0, xb0);
                a[mt][1] = relu_add2(x1, xb0);
                a[mt][2] = relu_add2(x2, xb1);
                a[mt][3] = relu_add2(x3, xb1);
            }
            const char* wp = w2f_base + (size_t)k * 16 * 32 * 8;
            #pragma unroll
            for (int n = 0; n < 8; n++) {
                uint2 bf = *(const uint2*)(wp + (size_t)n * 32 * 8);
                mma16816(acc[0][n], a[0], bf.x, bf.y);
                mma16816(acc[1][n], a[1], bf.x, bf.y);
            }
        }

        // epilogue: pooled[col] += relu(acc + b2), rows summed
        #pragma unroll
        for (int n = 0; n < 8; n++) {
            #pragma unroll
            for (int mt = 0; mt < 2; mt++) {
                pooled[n][0] += fmaxf(acc[mt][n][0] + b2c[n][0], 0.f)
                              + fmaxf(acc[mt][n][2] + b2c[n][0], 0.f);
                pooled[n][1] += fmaxf(acc[mt][n][1] + b2c[n][1], 0.f)
                              + fmaxf(acc[mt][n][3] + b2c[n][1], 0.f);
            }
        }
    };

    // --- software-pipelined tile loop (xb prefetch in registers, no barriers) ---
    uint32_t xbA[16], xbB[16];
    load_xb(xbA, cig);
    for (int t = 0; t < ntiles; t += 2) {
        if (t + 1 < ntiles) load_xb(xbB, cig + (t + 1) * CPG);
        compute_tile(xbA);
        if (t + 1 < ntiles) {
            if (t + 2 < ntiles) load_xb(xbA, cig + (t + 2) * CPG);
            compute_tile(xbB);
        }
    }

    // --- deterministic reduction: shfl over g, smem over warps, write g_part ---
    float* red = (float*)(smem + SOFF_RED);
    #pragma unroll
    for (int n = 0; n < 8; n++) {
        #pragma unroll
        for (int p = 0; p < 2; p++) {
            float v = pooled[n][p];
            v += __shfl_xor_sync(0xFFFFFFFFu, v, 4);
            v += __shfl_xor_sync(0xFFFFFFFFu, v, 8);
            v += __shfl_xor_sync(0xFFFFFFFFu, v, 16);
            if (lane < 4) red[wid * 64 + n * 8 + lane * 2 + p] = v;
        }
    }
    __syncthreads();

    if (tid < 128) {
        int col = tid;
        int wbase = (col >> 6) * 4;          // warps with this wn
        int cl = col & 63;
        float s = red[(wbase + 0) * 64 + cl] + red[(wbase + 1) * 64 + cl]
                + red[(wbase + 2) * 64 + cl] + red[(wbase + 3) * 64 + cl];
        g_part[blockIdx.x * H_ + col] = s;
    }
}

// =====================================================================
// Kernel 3: finish — pooled = S@W3 + N^2*b3 ; o = relu(pooled@V1+c1) ; out = o@V2+c2
// =====================================================================
__global__ void __launch_bounds__(128) finish_kernel(const float* __restrict__ W3,
                                                     const float* __restrict__ b3,
                                                     const float* __restrict__ V1,
                                                     const float* __restrict__ c1,
                                                     const float* __restrict__ V2,
                                                     const float* __restrict__ c2,
                                                     float* __restrict__ out) {
    int b = blockIdx.x, h = threadIdx.x;
    __shared__ float S[128], P[128], O[128];

    // sum per-CTA partials for this batch (CTAs b*72 .. b*72+71), fixed order
    float s = 0.f;
    #pragma unroll 8
    for (int c = 0; c < 4 * CPG; c++)
        s += g_part[(b * 4 * CPG + c) * H_ + h];
    S[h] = s;
    __syncthreads();

    float p = (float)(N_) * (float)(N_) * b3[h];
    #pragma unroll 8
    for (int kk = 0; kk < 128; kk++) p += S[kk] * W3[kk * H_ + h];
    P[h] = p;
    __syncthreads();

    float o = c1[h];
    #pragma unroll 8
    for (int kk = 0; kk < 128; kk++) o += P[kk] * V1[kk * H_ + h];
    O[h] = fmaxf(o, 0.f);
    __syncthreads();

    if (h < OUT_) {
        float r = c2[h];
        #pragma unroll 8
        for (int kk = 0; kk < 128; kk++) r += O[kk] * V2[kk * OUT_ + h];
        out[b * OUT_ + h] = r;
    }
}

// =====================================================================
extern "C" void kernel_launch(void* const* d_in, const int* in_sizes, int n_in,
                              void* d_out, int out_size) {
    (void)in_sizes; (void)n_in; (void)out_size;
    const float* x  = (const float*)d_in[0];
    const float* W1 = (const float*)d_in[1];
    const float* b1 = (const float*)d_in[2];
    const float* W2 = (const float*)d_in[3];
    const float* b2 = (const float*)d_in[4];
    const float* W3 = (const float*)d_in[5];
    const float* b3 = (const float*)d_in[6];
    const float* V1 = (const float*)d_in[7];
    const float* c1 = (const float*)d_in[8];
    const float* V2 = (const float*)d_in[9];
    const float* c2 = (const float*)d_in[10];
    float* out = (float*)d_out;

    cudaFuncSetAttribute(main_kernel, cudaFuncAttributeMaxDynamicSharedMemorySize, SMEM_BYTES);

    prep_kernel<<<(B_ * N_) / 8, 128>>>(x, W1, b1);
    main_kernel<<<GRID_MAIN, 256, SMEM_BYTES>>>(W2, b2);
    finish_kernel<<<B_, 128>>>(W3, b3, V1, c1, V2, c2, out);
}

// round 7
// speedup vs baseline: 1.0066x; 1.0066x over previous
#include <cuda_runtime.h>
#include <cuda_fp16.h>
#include <stdint.h>
#include <string.h>

// ---------------- problem constants ----------------
#define B_   2
#define N_   512
#define D_   64
#define H_   128
#define OUT_ 64
#define CPG  18                  // i-stride: CTAs per (b, j-block) group
#define GRID_MAIN (B_ * 4 * CPG) // 144 CTAs, ~1 per SM

// ---------------- device scratch (no allocs allowed) ----------------
__device__ __align__(16) __half g_xa [B_ * N_ * H_];   // x @ W1[:D]       (fp16)
__device__ __align__(16) __half g_xbp[B_ * N_ * H_];   // x @ W1[D:] + b1  (fp16)
__device__ float g_part[GRID_MAIN * H_];               // per-CTA pooled partials

__device__ __forceinline__ __half2 as_h2(uint32_t u) { __half2 h; memcpy(&h, &u, 4); return h; }
__device__ __forceinline__ uint32_t as_u32(__half2 h) { uint32_t u; memcpy(&u, &h, 4); return u; }

// relu(a + b) on packed half2
__device__ __forceinline__ uint32_t relu_add2(uint32_t a, uint32_t b) {
    __half2 z = __float2half2_rn(0.f);
    return as_u32(__hmax2(__hadd2(as_h2(a), as_h2(b)), z));
}

// m16n8k16 row.col fp16 -> fp32 HMMA (baseline PTX, assembles for sm_103)
__device__ __forceinline__ void mma16816(float* c, const uint32_t* a, uint32_t b0, uint32_t b1) {
    asm volatile(
        "mma.sync.aligned.m16n8k16.row.col.f32.f16.f16.f32 "
        "{%0,%1,%2,%3}, {%4,%5,%6,%7}, {%8,%9}, {%0,%1,%2,%3};"
        : "+f"(c[0]), "+f"(c[1]), "+f"(c[2]), "+f"(c[3])
        : "r"(a[0]), "r"(a[1]), "r"(a[2]), "r"(a[3]), "r"(b0), "r"(b1));
}

// ---------------- SMEM layout (dynamic) ----------------
// W2F : 0      32768  (W2 fragments, [k8][nt16][lane32] x 8B)
// XA  : 32768  34816  (128 rows x 272B padded fp16; staged once, read to regs)
// RED : 67584  2048   (8 warps x 64 cols fp32)
// B2  : 69632  512
#define SOFF_W2F 0
#define SOFF_XA  32768
#define SOFF_RED 67584
#define SOFF_B2  69632
#define XA_STRIDE 272
#define SMEM_BYTES (69632 + 512)

// =====================================================================
// Kernel 1: prep — xa = x @ W1[:64] (fp16), xbp = x @ W1[64:] + b1 (fp16)
// 256 blocks x 256 threads; threads 0-127 compute xa, 128-255 compute xbp.
// 64 W1 regs per thread (not 128) -> no spills, 4x occupancy of old version.
// =====================================================================
__global__ void __launch_bounds__(256) prep_kernel(const float* __restrict__ x,
                                                   const float* __restrict__ W1,
                                                   const float* __restrict__ b1) {
    __shared__ float xs[4][64];
    int tid  = threadIdx.x;
    int h    = tid & 127;
    int half = tid >> 7;                  // 0 -> xa, 1 -> xbp
    int row0 = blockIdx.x * 4;

    for (int q = tid; q < 4 * 64; q += 256)
        xs[q >> 6][q & 63] = x[row0 * 64 + q];

    float w[64];
    #pragma unroll
    for (int d = 0; d < 64; d++)
        w[d] = W1[(d + half * 64) * H_ + h];
    float bb = half ? b1[h] : 0.f;
    __syncthreads();

    #pragma unroll
    for (int rr = 0; rr < 4; rr++) {
        float s = bb;
        #pragma unroll
        for (int d = 0; d < 64; d++) s += xs[rr][d] * w[d];
        int row = row0 + rr;
        if (half) g_xbp[row * H_ + h] = __float2half(s);
        else      g_xa [row * H_ + h] = __float2half(s);
    }
}

// =====================================================================
// Kernel 2: main — per (b, jb, cig) CTA, loop i-tiles (i = cig + t*CPG):
//   xa tile held entirely in REGISTERS (invariant across tiles)
//   A-fragments a = relu(xa + xb[i]) built in registers
//   acc = a @ W2 via mma.sync (fp32 register accumulators)
//   pooled += relu(acc + b2); per-CTA partial to g_part (deterministic)
// =====================================================================
__global__ void __launch_bounds__(256, 1) main_kernel(const float* __restrict__ W2,
                                                      const float* __restrict__ b2) {
    extern __shared__ char smem[];

    int tid  = threadIdx.x;
    int wid  = tid >> 5;
    int lane = tid & 31;
    int tig  = lane & 3;      // k-pair / n-parity selector
    int g    = lane >> 2;     // row within 8
    int wn   = wid >> 2;      // warp col half: 0 -> cols 0..63, 1 -> 64..127
    int wm   = wid & 3;       // warp row quarter

    int grp = blockIdx.x / CPG;   // 0..7 : (b, jb)
    int cig = blockIdx.x % CPG;
    int b   = grp >> 2;
    int jb  = grp & 3;
    int ntiles = (N_ - cig + CPG - 1) / CPG;   // 28 or 29

    // --- pack W2 into fragment-ordered smem: entry (k, nt, lane) -> 8 bytes ---
    for (int idx = tid; idx < 8 * 16 * 32; idx += 256) {
        int li = idx & 31, nt = (idx >> 5) & 15, k = idx >> 9;
        int ltig = li & 3, lg = li >> 2;
        int col = nt * 8 + lg;
        int r0 = k * 16 + ltig * 2;
        uint32_t v0 = as_u32(__floats2half2_rn(W2[r0 * H_ + col],       W2[(r0 + 1) * H_ + col]));
        uint32_t v1 = as_u32(__floats2half2_rn(W2[(r0 + 8) * H_ + col], W2[(r0 + 9) * H_ + col]));
        *(uint2*)(smem + SOFF_W2F + idx * 8) = make_uint2(v0, v1);
    }

    // --- stage xa tile (b, jb): 128 rows x 128 fp16, 272B padded stride ---
    {
        const float4* xag = (const float4*)(g_xa + (size_t)(b * N_ + jb * 128) * H_);
        for (int q = tid; q < 128 * 16; q += 256) {
            int r = q >> 4, f = q & 15;
            *(float4*)(smem + SOFF_XA + r * XA_STRIDE + f * 16) = xag[q];
        }
    }

    // --- b2 to smem ---
    if (tid < 128) *(float*)(smem + SOFF_B2 + tid * 4) = b2[tid];

    __syncthreads();

    // --- hoist this thread's xa fragments into registers (invariant) ---
    // rows: wm*32 + mt*16 + g (+8); cols: k*16 + tig*2 (+8)
    uint32_t xar[8][8];   // [k][mt*4 + frag]
    {
        const char* xa_base = smem + SOFF_XA + (wm * 32 + g) * XA_STRIDE + tig * 4;
        #pragma unroll
        for (int k = 0; k < 8; k++) {
            #pragma unroll
            for (int mt = 0; mt < 2; mt++) {
                const char* p0 = xa_base + mt * 16 * XA_STRIDE + k * 32;
                const char* p1 = p0 + 8 * XA_STRIDE;
                xar[k][mt * 4 + 0] = *(const uint32_t*)(p0);
                xar[k][mt * 4 + 1] = *(const uint32_t*)(p1);
                xar[k][mt * 4 + 2] = *(const uint32_t*)(p0 + 16);
                xar[k][mt * 4 + 3] = *(const uint32_t*)(p1 + 16);
            }
        }
    }

    const char* w2f_base = smem + SOFF_W2F + (size_t)(wn * 8) * 32 * 8 + lane * 8;
    const uint32_t* xbp_rows = (const uint32_t*)(g_xbp + (size_t)(b * N_) * H_);
    const float* b2s = (const float*)(smem + SOFF_B2);

    float pooled[8][2];
    #pragma unroll
    for (int n = 0; n < 8; n++) { pooled[n][0] = 0.f; pooled[n][1] = 0.f; }

    // xb loader: 16 half2 regs for one i-row (words k*8+tig and k*8+tig+4)
    auto load_xb = [&](uint32_t* xb, int i) {
        const uint32_t* row = xbp_rows + (size_t)i * (H_ / 2);
        #pragma unroll
        for (int k = 0; k < 8; k++) {
            xb[k * 2]     = __ldg(row + k * 8 + tig);
            xb[k * 2 + 1] = __ldg(row + k * 8 + tig + 4);
        }
    };

    auto compute_tile = [&](const uint32_t* xb) {
        float acc[2][8][4];
        #pragma unroll
        for (int mt = 0; mt < 2; mt++)
            #pragma unroll
            for (int n = 0; n < 8; n++)
                #pragma unroll
                for (int c = 0; c < 4; c++) acc[mt][n][c] = 0.f;

        #pragma unroll
        for (int k = 0; k < 8; k++) {
            uint32_t xb0 = xb[k * 2], xb1 = xb[k * 2 + 1];
            uint32_t a[2][4];
            #pragma unroll
            for (int mt = 0; mt < 2; mt++) {
                a[mt][0] = relu_add2(xar[k][mt * 4 + 0], xb0);
                a[mt][1] = relu_add2(xar[k][mt * 4 + 1], xb0);
                a[mt][2] = relu_add2(xar[k][mt * 4 + 2], xb1);
                a[mt][3] = relu_add2(xar[k][mt * 4 + 3], xb1);
            }
            const char* wp = w2f_base + (size_t)k * 16 * 32 * 8;
            #pragma unroll
            for (int n = 0; n < 8; n++) {
                uint2 bf = *(const uint2*)(wp + (size_t)n * 32 * 8);
                mma16816(acc[0][n], a[0], bf.x, bf.y);
                mma16816(acc[1][n], a[1], bf.x, bf.y);
            }
        }

        // epilogue: pooled[col] += relu(acc + b2), rows summed
        #pragma unroll
        for (int n = 0; n < 8; n++) {
            float bc0 = b2s[wn * 64 + n * 8 + tig * 2];
            float bc1 = b2s[wn * 64 + n * 8 + tig * 2 + 1];
            #pragma unroll
            for (int mt = 0; mt < 2; mt++) {
                pooled[n][0] += fmaxf(acc[mt][n][0] + bc0, 0.f)
                              + fmaxf(acc[mt][n][2] + bc0, 0.f);
                pooled[n][1] += fmaxf(acc[mt][n][1] + bc1, 0.f)
                              + fmaxf(acc[mt][n][3] + bc1, 0.f);
            }
        }
    };

    // --- software-pipelined tile loop (xb prefetch in regs, no barriers) ---
    uint32_t xbA[16], xbB[16];
    load_xb(xbA, cig);
    for (int t = 0; t < ntiles; t += 2) {
        if (t + 1 < ntiles) load_xb(xbB, cig + (t + 1) * CPG);
        compute_tile(xbA);
        if (t + 1 < ntiles) {
            if (t + 2 < ntiles) load_xb(xbA, cig + (t + 2) * CPG);
            compute_tile(xbB);
        }
    }

    // --- deterministic reduction: shfl over rows, smem over warps ---
    float* red = (float*)(smem + SOFF_RED);
    #pragma unroll
    for (int n = 0; n < 8; n++) {
        #pragma unroll
        for (int p = 0; p < 2; p++) {
            float v = pooled[n][p];
            v += __shfl_xor_sync(0xFFFFFFFFu, v, 4);
            v += __shfl_xor_sync(0xFFFFFFFFu, v, 8);
            v += __shfl_xor_sync(0xFFFFFFFFu, v, 16);
            if (lane < 4) red[wid * 64 + n * 8 + lane * 2 + p] = v;
        }
    }
    __syncthreads();

    if (tid < 128) {
        int col = tid;
        int wbase = (col >> 6) * 4;
        int cl = col & 63;
        float s = red[(wbase + 0) * 64 + cl] + red[(wbase + 1) * 64 + cl]
                + red[(wbase + 2) * 64 + cl] + red[(wbase + 3) * 64 + cl];
        g_part[blockIdx.x * H_ + col] = s;
    }
}

// =====================================================================
// Kernel 3: finish — pooled = S@W3 + N^2*b3 ; o = relu(pooled@V1+c1) ; out = o@V2+c2
// =====================================================================
__global__ void __launch_bounds__(128) finish_kernel(const float* __restrict__ W3,
                                                     const float* __restrict__ b3,
                                                     const float* __restrict__ V1,
                                                     const float* __restrict__ c1,
                                                     const float* __restrict__ V2,
                                                     const float* __restrict__ c2,
                                                     float* __restrict__ out) {
    int b = blockIdx.x, h = threadIdx.x;
    __shared__ float S[128], P[128], O[128];

    float s = 0.f;
    #pragma unroll 8
    for (int c = 0; c < 4 * CPG; c++)
        s += g_part[(b * 4 * CPG + c) * H_ + h];
    S[h] = s;
    __syncthreads();

    float p = (float)(N_) * (float)(N_) * b3[h];
    #pragma unroll 8
    for (int kk = 0; kk < 128; kk++) p += S[kk] * W3[kk * H_ + h];
    P[h] = p;
    __syncthreads();

    float o = c1[h];
    #pragma unroll 8
    for (int kk = 0; kk < 128; kk++) o += P[kk] * V1[kk * H_ + h];
    O[h] = fmaxf(o, 0.f);
    __syncthreads();

    if (h < OUT_) {
        float r = c2[h];
        #pragma unroll 8
        for (int kk = 0; kk < 128; kk++) r += O[kk] * V2[kk * OUT_ + h];
        out[b * OUT_ + h] = r;
    }
}

// =====================================================================
extern "C" void kernel_launch(void* const* d_in, const int* in_sizes, int n_in,
                              void* d_out, int out_size) {
    (void)in_sizes; (void)n_in; (void)out_size;
    const float* x  = (const float*)d_in[0];
    const float* W1 = (const float*)d_in[1];
    const float* b1 = (const float*)d_in[2];
    const float* W2 = (const float*)d_in[3];
    const float* b2 = (const float*)d_in[4];
    const float* W3 = (const float*)d_in[5];
    const float* b3 = (const float*)d_in[6];
    const float* V1 = (const float*)d_in[7];
    const float* c1 = (const float*)d_in[8];
    const float* V2 = (const float*)d_in[9];
    const float* c2 = (const float*)d_in[10];
    float* out = (float*)d_out;

    cudaFuncSetAttribute(main_kernel, cudaFuncAttributeMaxDynamicSharedMemorySize, SMEM_BYTES);

    prep_kernel<<<(B_ * N_) / 4, 256>>>(x, W1, b1);
    main_kernel<<<GRID_MAIN, 256, SMEM_BYTES>>>(W2, b2);
    finish_kernel<<<B_, 128>>>(W3, b3, V1, c1, V2, c2, out);
}

// round 10
// speedup vs baseline: 1.0529x; 1.0460x over previous
#include <cuda_runtime.h>
#include <cuda_fp16.h>
#include <stdint.h>
#include <string.h>

// ---------------- problem constants ----------------
#define B_   2
#define N_   512
#define D_   64
#define H_   128
#define OUT_ 64
#define CPG  18                  // i-stride: CTAs per (b, j-block) group
#define GRID_MAIN (B_ * 4 * CPG) // 144 CTAs, ~1 per SM

// ---------------- device scratch (no allocs allowed) ----------------
__device__ __align__(16) __half g_xa [B_ * N_ * H_];   // x @ W1[:D]       (fp16)
__device__ __align__(16) __half g_xbp[B_ * N_ * H_];   // x @ W1[D:] + b1  (fp16)
__device__ float g_part[GRID_MAIN * H_];               // per-CTA pooled partials

__device__ __forceinline__ __half2 as_h2(uint32_t u) { __half2 h; memcpy(&h, &u, 4); return h; }
__device__ __forceinline__ uint32_t as_u32(__half2 h) { uint32_t u; memcpy(&u, &h, 4); return u; }

// relu(a + b) on packed half2
__device__ __forceinline__ uint32_t relu_add2(uint32_t a, uint32_t b) {
    __half2 z = __float2half2_rn(0.f);
    return as_u32(__hmax2(__hadd2(as_h2(a), as_h2(b)), z));
}

// m16n8k16 row.col fp16 x fp16 -> fp16 accumulate (baseline PTX, sm_80+)
__device__ __forceinline__ void mma16816h(uint32_t* c, const uint32_t* a, uint32_t b0, uint32_t b1) {
    asm volatile(
        "mma.sync.aligned.m16n8k16.row.col.f16.f16.f16.f16 "
        "{%0,%1}, {%2,%3,%4,%5}, {%6,%7}, {%0,%1};"
        : "+r"(c[0]), "+r"(c[1])
        : "r"(a[0]), "r"(a[1]), "r"(a[2]), "r"(a[3]), "r"(b0), "r"(b1));
}

// ---------------- SMEM layout (dynamic) ----------------
// W2F : 0      32768  (W2 fragments, [k8][nt16][lane32] x 8B)
// XA  : 32768  34816  (128 rows x 272B padded fp16; staged once, read to regs)
// RED : 67584  2048   (8 warps x 64 cols fp32)
// B2  : 69632  512
#define SOFF_W2F 0
#define SOFF_XA  32768
#define SOFF_RED 67584
#define SOFF_B2  69632
#define XA_STRIDE 272
#define SMEM_BYTES (69632 + 512)

// =====================================================================
// Kernel 1: prep — xa = x @ W1[:64] (fp16), xbp = x @ W1[64:] + b1 (fp16)
// 256 blocks x 256 threads; 8 parallel partial chains per row to kill
// the serial-FFMA latency wall (issue was 15% at R7).
// =====================================================================
__global__ void __launch_bounds__(256) prep_kernel(const float* __restrict__ x,
                                                   const float* __restrict__ W1,
                                                   const float* __restrict__ b1) {
    __shared__ float xs[4][64];
    int tid  = threadIdx.x;
    int h    = tid & 127;
    int half = tid >> 7;                  // 0 -> xa, 1 -> xbp
    int row0 = blockIdx.x * 4;

    for (int q = tid; q < 4 * 64; q += 256)
        xs[q >> 6][q & 63] = x[row0 * 64 + q];

    float w[64];
    #pragma unroll
    for (int d = 0; d < 64; d++)
        w[d] = W1[(d + half * 64) * H_ + h];
    float bb = half ? b1[h] : 0.f;
    __syncthreads();

    #pragma unroll
    for (int rr = 0; rr < 4; rr++) {
        float p[8];
        #pragma unroll
        for (int j = 0; j < 8; j++) p[j] = 0.f;
        #pragma unroll
        for (int d8 = 0; d8 < 8; d8++)
            #pragma unroll
            for (int j = 0; j < 8; j++)
                p[j] += xs[rr][d8 * 8 + j] * w[d8 * 8 + j];
        float s = bb + (((p[0] + p[1]) + (p[2] + p[3])) + ((p[4] + p[5]) + (p[6] + p[7])));
        int row = row0 + rr;
        if (half) g_xbp[row * H_ + h] = __float2half(s);
        else      g_xa [row * H_ + h] = __float2half(s);
    }
}

// =====================================================================
// Kernel 2: main — per (b, jb, cig) CTA, loop i-tiles (i = cig + t*CPG):
//   xa tile in registers (invariant across tiles)
//   A-fragments a = relu(xa + xb[i]); acc = a @ W2 via mma.sync
//   *** fp16 accumulators *** (tests 2x fallback-HMMA rate hypothesis)
//   pooled += relu(acc + b2) in fp32; per-CTA partial -> g_part
// =====================================================================
__global__ void __launch_bounds__(256, 1) main_kernel(const float* __restrict__ W2,
                                                      const float* __restrict__ b2) {
    extern __shared__ char smem[];

    int tid  = threadIdx.x;
    int wid  = tid >> 5;
    int lane = tid & 31;
    int tig  = lane & 3;      // k-pair / n-parity selector
    int g    = lane >> 2;     // row within 8
    int wn   = wid >> 2;      // warp col half: 0 -> cols 0..63, 1 -> 64..127
    int wm   = wid & 3;       // warp row quarter

    int grp = blockIdx.x / CPG;   // 0..7 : (b, jb)
    int cig = blockIdx.x % CPG;
    int b   = grp >> 2;
    int jb  = grp & 3;
    int ntiles = (N_ - cig + CPG - 1) / CPG;   // 28 or 29

    // --- pack W2 into fragment-ordered smem: entry (k, nt, lane) -> 8 bytes ---
    for (int idx = tid; idx < 8 * 16 * 32; idx += 256) {
        int li = idx & 31, nt = (idx >> 5) & 15, k = idx >> 9;
        int ltig = li & 3, lg = li >> 2;
        int col = nt * 8 + lg;
        int r0 = k * 16 + ltig * 2;
        uint32_t v0 = as_u32(__floats2half2_rn(W2[r0 * H_ + col],       W2[(r0 + 1) * H_ + col]));
        uint32_t v1 = as_u32(__floats2half2_rn(W2[(r0 + 8) * H_ + col], W2[(r0 + 9) * H_ + col]));
        *(uint2*)(smem + SOFF_W2F + idx * 8) = make_uint2(v0, v1);
    }

    // --- stage xa tile (b, jb): 128 rows x 128 fp16, 272B padded stride ---
    {
        const float4* xag = (const float4*)(g_xa + (size_t)(b * N_ + jb * 128) * H_);
        for (int q = tid; q < 128 * 16; q += 256) {
            int r = q >> 4, f = q & 15;
            *(float4*)(smem + SOFF_XA + r * XA_STRIDE + f * 16) = xag[q];
        }
    }

    // --- b2 to smem (fp32) ---
    if (tid < 128) *(float*)(smem + SOFF_B2 + tid * 4) = b2[tid];

    __syncthreads();

    // --- hoist this thread's xa fragments into registers (invariant) ---
    uint32_t xar[8][8];   // [k][mt*4 + frag]
    {
        const char* xa_base = smem + SOFF_XA + (wm * 32 + g) * XA_STRIDE + tig * 4;
        #pragma unroll
        for (int k = 0; k < 8; k++) {
            #pragma unroll
            for (int mt = 0; mt < 2; mt++) {
                const char* p0 = xa_base + mt * 16 * XA_STRIDE + k * 32;
                const char* p1 = p0 + 8 * XA_STRIDE;
                xar[k][mt * 4 + 0] = *(const uint32_t*)(p0);
                xar[k][mt * 4 + 1] = *(const uint32_t*)(p1);
                xar[k][mt * 4 + 2] = *(const uint32_t*)(p0 + 16);
                xar[k][mt * 4 + 3] = *(const uint32_t*)(p1 + 16);
            }
        }
    }

    // --- per-thread b2 half2 biases for the epilogue ---
    uint32_t b2h[8];
    {
        const float* b2s = (const float*)(smem + SOFF_B2);
        #pragma unroll
        for (int n = 0; n < 8; n++) {
            int col = wn * 64 + n * 8 + tig * 2;
            b2h[n] = as_u32(__floats2half2_rn(b2s[col], b2s[col + 1]));
        }
    }

    const char* w2f_base = smem + SOFF_W2F + (size_t)(wn * 8) * 32 * 8 + lane * 8;
    const uint32_t* xbp_rows = (const uint32_t*)(g_xbp + (size_t)(b * N_) * H_);

    float pooled[8][2];
    #pragma unroll
    for (int n = 0; n < 8; n++) { pooled[n][0] = 0.f; pooled[n][1] = 0.f; }

    auto load_xb = [&](uint32_t* xb, int i) {
        const uint32_t* row = xbp_rows + (size_t)i * (H_ / 2);
        #pragma unroll
        for (int k = 0; k < 8; k++) {
            xb[k * 2]     = __ldg(row + k * 8 + tig);
            xb[k * 2 + 1] = __ldg(row + k * 8 + tig + 4);
        }
    };

    auto compute_tile = [&](const uint32_t* xb) {
        // fp16 accumulators: [mt][n] = {rows g | cols 2tig..+1, rows g+8 | same}
        uint32_t acc[2][8][2];
        #pragma unroll
        for (int mt = 0; mt < 2; mt++)
            #pragma unroll
            for (int n = 0; n < 8; n++) { acc[mt][n][0] = 0u; acc[mt][n][1] = 0u; }

        #pragma unroll
        for (int k = 0; k < 8; k++) {
            uint32_t xb0 = xb[k * 2], xb1 = xb[k * 2 + 1];
            uint32_t a[2][4];
            #pragma unroll
            for (int mt = 0; mt < 2; mt++) {
                a[mt][0] = relu_add2(xar[k][mt * 4 + 0], xb0);
                a[mt][1] = relu_add2(xar[k][mt * 4 + 1], xb0);
                a[mt][2] = relu_add2(xar[k][mt * 4 + 2], xb1);
                a[mt][3] = relu_add2(xar[k][mt * 4 + 3], xb1);
            }
            const char* wp = w2f_base + (size_t)k * 16 * 32 * 8;
            #pragma unroll
            for (int n = 0; n < 8; n++) {
                uint2 bf = *(const uint2*)(wp + (size_t)n * 32 * 8);
                mma16816h(acc[0][n], a[0], bf.x, bf.y);
                mma16816h(acc[1][n], a[1], bf.x, bf.y);
            }
        }

        // epilogue: pooled[col] += relu(acc + b2) over the 4 row-fragments (fp32)
        __half2 z = __float2half2_rn(0.f);
        #pragma unroll
        for (int n = 0; n < 8; n++) {
            #pragma unroll
            for (int mt = 0; mt < 2; mt++) {
                __half2 r0 = __hmax2(__hadd2(as_h2(acc[mt][n][0]), as_h2(b2h[n])), z);
                __half2 r1 = __hmax2(__hadd2(as_h2(acc[mt][n][1]), as_h2(b2h[n])), z);
                float2 f0 = __half22float2(r0);
                float2 f1 = __half22float2(r1);
                pooled[n][0] += f0.x + f1.x;
                pooled[n][1] += f0.y + f1.y;
            }
        }
    };

    // --- software-pipelined tile loop (xb prefetch in regs, no barriers) ---
    uint32_t xbA[16], xbB[16];
    load_xb(xbA, cig);
    for (int t = 0; t < ntiles; t += 2) {
        if (t + 1 < ntiles) load_xb(xbB, cig + (t + 1) * CPG);
        compute_tile(xbA);
        if (t + 1 < ntiles) {
            if (t + 2 < ntiles) load_xb(xbA, cig + (t + 2) * CPG);
            compute_tile(xbB);
        }
    }

    // --- deterministic reduction: shfl over rows, smem over warps ---
    float* red = (float*)(smem + SOFF_RED);
    #pragma unroll
    for (int n = 0; n < 8; n++) {
        #pragma unroll
        for (int p = 0; p < 2; p++) {
            float v = pooled[n][p];
            v += __shfl_xor_sync(0xFFFFFFFFu, v, 4);
            v += __shfl_xor_sync(0xFFFFFFFFu, v, 8);
            v += __shfl_xor_sync(0xFFFFFFFFu, v, 16);
            if (lane < 4) red[wid * 64 + n * 8 + lane * 2 + p] = v;
        }
    }
    __syncthreads();

    if (tid < 128) {
        int col = tid;
        int wbase = (col >> 6) * 4;
        int cl = col & 63;
        float s = red[(wbase + 0) * 64 + cl] + red[(wbase + 1) * 64 + cl]
                + red[(wbase + 2) * 64 + cl] + red[(wbase + 3) * 64 + cl];
        g_part[blockIdx.x * H_ + col] = s;
    }
}

// =====================================================================
// Kernel 3: finish — pooled = S@W3 + N^2*b3 ; o = relu(pooled@V1+c1) ; out = o@V2+c2
// =====================================================================
__global__ void __launch_bounds__(128) finish_kernel(const float* __restrict__ W3,
                                                     const float* __restrict__ b3,
                                                     const float* __restrict__ V1,
                                                     const float* __restrict__ c1,
                                                     const float* __restrict__ V2,
                                                     const float* __restrict__ c2,
                                                     float* __restrict__ out) {
    int b = blockIdx.x, h = threadIdx.x;
    __shared__ float S[128], P[128], O[128];

    float s = 0.f;
    #pragma unroll 8
    for (int c = 0; c < 4 * CPG; c++)
        s += g_part[(b * 4 * CPG + c) * H_ + h];
    S[h] = s;
    __syncthreads();

    float p = (float)(N_) * (float)(N_) * b3[h];
    #pragma unroll 8
    for (int kk = 0; kk < 128; kk++) p += S[kk] * W3[kk * H_ + h];
    P[h] = p;
    __syncthreads();

    float o = c1[h];
    #pragma unroll 8
    for (int kk = 0; kk < 128; kk++) o += P[kk] * V1[kk * H_ + h];
    O[h] = fmaxf(o, 0.f);
    __syncthreads();

    if (h < OUT_) {
        float r = c2[h];
        #pragma unroll 8
        for (int kk = 0; kk < 128; kk++) r += O[kk] * V2[kk * OUT_ + h];
        out[b * OUT_ + h] = r;
    }
}

// =====================================================================
extern "C" void kernel_launch(void* const* d_in, const int* in_sizes, int n_in,
                              void* d_out, int out_size) {
    (void)in_sizes; (void)n_in; (void)out_size;
    const float* x  = (const float*)d_in[0];
    const float* W1 = (const float*)d_in[1];
    const float* b1 = (const float*)d_in[2];
    const float* W2 = (const float*)d_in[3];
    const float* b2 = (const float*)d_in[4];
    const float* W3 = (const float*)d_in[5];
    const float* b3 = (const float*)d_in[6];
    const float* V1 = (const float*)d_in[7];
    const float* c1 = (const float*)d_in[8];
    const float* V2 = (const float*)d_in[9];
    const float* c2 = (const float*)d_in[10];
    float* out = (float*)d_out;

    cudaFuncSetAttribute(main_kernel, cudaFuncAttributeMaxDynamicSharedMemorySize, SMEM_BYTES);

    prep_kernel<<<(B_ * N_) / 4, 256>>>(x, W1, b1);
    main_kernel<<<GRID_MAIN, 256, SMEM_BYTES>>>(W2, b2);
    finish_kernel<<<B_, 128>>>(W3, b3, V1, c1, V2, c2, out);
}